// round 2
// baseline (speedup 1.0000x reference)
#include <cuda_runtime.h>
#include <math.h>

#define SEQ    16384
#define HIDDEN 4096
#define NHEADS 32
#define DH     128
#define RLAT   64

// Scratch (allocation-free rule: static device globals)
__device__ float g_bufA[(size_t)SEQ * HIDDEN];
__device__ float g_bufB[(size_t)SEQ * HIDDEN];

// ---------------------------------------------------------------------------
// Tiled fp32 GEMM: C[M,N] = epilogue(A[M,K] @ B[K,N])
// BM=BN=128, BK=16, 256 threads, 8x8 per-thread tile.
// Block mapping: y (N-tile) fastest => weight matrix B stays L2-resident,
// each A tile read from DRAM once.
// ---------------------------------------------------------------------------

__device__ __forceinline__ float gelu_exact(float x) {
    return 0.5f * x * (1.0f + erff(x * 0.70710678118654752f));
}

template <bool HASBIAS, bool GELU, bool RESID>
__global__ __launch_bounds__(256)
void gemm_kernel(const float* __restrict__ A, const float* __restrict__ B,
                 const float* __restrict__ bias, const float* __restrict__ resid,
                 float* __restrict__ C, int M, int N, int K)
{
    __shared__ float As[16][128];
    __shared__ float Bs[16][128];

    const int nyb = N >> 7;
    const int xb = blockIdx.x / nyb;
    const int yb = blockIdx.x % nyb;
    const int rowBase = xb << 7;
    const int colBase = yb << 7;

    const int tid = threadIdx.x;
    const int ty = tid >> 4;   // 0..15
    const int tx = tid & 15;   // 0..15

    // global load mapping
    const int a_row = tid >> 2;     // 0..63 (+64)
    const int a_k4  = tid & 3;      // float4 slot in BK=16
    const int b_k   = tid >> 5;     // 0..7 (+8)
    const int b_c4  = tid & 31;     // float4 slot in 128 cols

    const float* Ap = A + (size_t)rowBase * K;
    const float* Bp = B + colBase;

    float acc[8][8];
#pragma unroll
    for (int i = 0; i < 8; i++)
#pragma unroll
        for (int j = 0; j < 8; j++) acc[i][j] = 0.0f;

    for (int kt = 0; kt < K; kt += 16) {
#pragma unroll
        for (int p = 0; p < 2; p++) {
            int r = a_row + (p << 6);
            float4 v = *(const float4*)(Ap + (size_t)r * K + kt + (a_k4 << 2));
            As[(a_k4 << 2) + 0][r] = v.x;
            As[(a_k4 << 2) + 1][r] = v.y;
            As[(a_k4 << 2) + 2][r] = v.z;
            As[(a_k4 << 2) + 3][r] = v.w;
        }
#pragma unroll
        for (int p = 0; p < 2; p++) {
            int kk = b_k + (p << 3);
            float4 v = *(const float4*)(Bp + (size_t)(kt + kk) * N + (b_c4 << 2));
            *(float4*)&Bs[kk][b_c4 << 2] = v;
        }
        __syncthreads();

#pragma unroll
        for (int k = 0; k < 16; k++) {
            float a[8], b[8];
            *(float4*)&a[0] = *(const float4*)&As[k][ty << 2];
            *(float4*)&a[4] = *(const float4*)&As[k][64 + (ty << 2)];
            *(float4*)&b[0] = *(const float4*)&Bs[k][tx << 2];
            *(float4*)&b[4] = *(const float4*)&Bs[k][64 + (tx << 2)];
#pragma unroll
            for (int i = 0; i < 8; i++)
#pragma unroll
                for (int j = 0; j < 8; j++)
                    acc[i][j] = fmaf(a[i], b[j], acc[i][j]);
        }
        __syncthreads();
    }

    // epilogue: rows ty*4 + (i&3) + (i>>2)*64 ; cols tx*4 + (j&3) + (j>>2)*64
#pragma unroll
    for (int i = 0; i < 8; i++) {
        int row = rowBase + (ty << 2) + (i & 3) + ((i >> 2) << 6);
#pragma unroll
        for (int jh = 0; jh < 2; jh++) {
            int col = colBase + (tx << 2) + (jh << 6);
            float4 v;
            v.x = acc[i][jh * 4 + 0];
            v.y = acc[i][jh * 4 + 1];
            v.z = acc[i][jh * 4 + 2];
            v.w = acc[i][jh * 4 + 3];
            if (HASBIAS) {
                float4 bv = *(const float4*)(bias + col);
                v.x += bv.x; v.y += bv.y; v.z += bv.z; v.w += bv.w;
            }
            if (GELU) {
                v.x = gelu_exact(v.x);
                v.y = gelu_exact(v.y);
                v.z = gelu_exact(v.z);
                v.w = gelu_exact(v.w);
            }
            if (RESID) {
                float4 rv = *(const float4*)(resid + (size_t)row * N + col);
                v.x += rv.x; v.y += rv.y; v.z += rv.z; v.w += rv.w;
            }
            *(float4*)(C + (size_t)row * N + col) = v;
        }
    }
}

// ---------------------------------------------------------------------------
// Fused kernel 1:  xq = (query @ wq) * R^-0.5  ->  latent attention  -> tmp
// Each N-tile (128 cols) == one head. Attention over R=64 latents done in the
// epilogue against kv_latent columns of the same head (kv is tiny, L2-hot).
// ---------------------------------------------------------------------------

#define XQ_PITCH 132
#define FUSED_SMEM_FLOATS (128 * XQ_PITCH + 64 * XQ_PITCH + 8 * 64)

__global__ __launch_bounds__(256)
void fused_qk_attn_kernel(const float* __restrict__ A,   // query [SEQ,HIDDEN]
                          const float* __restrict__ B,   // wq [HIDDEN,HIDDEN]
                          const float* __restrict__ kv,  // kv_latent [RLAT,HIDDEN]
                          float* __restrict__ C)         // attn out [SEQ,HIDDEN]
{
    extern __shared__ float smem[];
    float (*As)[128] = (float(*)[128])smem;
    float (*Bs)[128] = (float(*)[128])(smem + 16 * 128);

    const int K = HIDDEN, N = HIDDEN;
    const int nyb = NHEADS;             // 32 N-tiles == heads
    const int xb = blockIdx.x / nyb;
    const int h  = blockIdx.x % nyb;
    const int rowBase = xb << 7;
    const int colBase = h * DH;

    const int tid = threadIdx.x;
    const int ty = tid >> 4;
    const int tx = tid & 15;

    const int a_row = tid >> 2;
    const int a_k4  = tid & 3;
    const int b_k   = tid >> 5;
    const int b_c4  = tid & 31;

    const float* Ap = A + (size_t)rowBase * K;
    const float* Bp = B + colBase;

    float acc[8][8];
#pragma unroll
    for (int i = 0; i < 8; i++)
#pragma unroll
        for (int j = 0; j < 8; j++) acc[i][j] = 0.0f;

    for (int kt = 0; kt < K; kt += 16) {
#pragma unroll
        for (int p = 0; p < 2; p++) {
            int r = a_row + (p << 6);
            float4 v = *(const float4*)(Ap + (size_t)r * K + kt + (a_k4 << 2));
            As[(a_k4 << 2) + 0][r] = v.x;
            As[(a_k4 << 2) + 1][r] = v.y;
            As[(a_k4 << 2) + 2][r] = v.z;
            As[(a_k4 << 2) + 3][r] = v.w;
        }
#pragma unroll
        for (int p = 0; p < 2; p++) {
            int kk = b_k + (p << 3);
            float4 v = *(const float4*)(Bp + (size_t)(kt + kk) * N + (b_c4 << 2));
            *(float4*)&Bs[kk][b_c4 << 2] = v;
        }
        __syncthreads();
#pragma unroll
        for (int k = 0; k < 16; k++) {
            float a[8], b[8];
            *(float4*)&a[0] = *(const float4*)&As[k][ty << 2];
            *(float4*)&a[4] = *(const float4*)&As[k][64 + (ty << 2)];
            *(float4*)&b[0] = *(const float4*)&Bs[k][tx << 2];
            *(float4*)&b[4] = *(const float4*)&Bs[k][64 + (tx << 2)];
#pragma unroll
            for (int i = 0; i < 8; i++)
#pragma unroll
                for (int j = 0; j < 8; j++)
                    acc[i][j] = fmaf(a[i], b[j], acc[i][j]);
        }
        __syncthreads();
    }

    // ---- attention epilogue ----
    float* xq  = smem;                         // [128][XQ_PITCH]
    float* kvs = smem + 128 * XQ_PITCH;        // [64][XQ_PITCH]
    float* ps  = kvs + 64 * XQ_PITCH;          // [8][64]

    const float scale = 0.125f;  // R^-0.5, R=64
#pragma unroll
    for (int i = 0; i < 8; i++) {
        int r = (ty << 2) + (i & 3) + ((i >> 2) << 6);
#pragma unroll
        for (int jh = 0; jh < 2; jh++) {
            int c = (tx << 2) + (jh << 6);
            float4 v;
            v.x = acc[i][jh * 4 + 0] * scale;
            v.y = acc[i][jh * 4 + 1] * scale;
            v.z = acc[i][jh * 4 + 2] * scale;
            v.w = acc[i][jh * 4 + 3] * scale;
            *(float4*)&xq[r * XQ_PITCH + c] = v;
        }
    }
    // load kv head slice: [64][128]
    for (int idx = tid; idx < RLAT * 32; idx += 256) {
        int r = idx >> 5, d4 = idx & 31;
        float4 v = *(const float4*)(kv + (size_t)r * HIDDEN + colBase + (d4 << 2));
        *(float4*)&kvs[r * XQ_PITCH + (d4 << 2)] = v;
    }
    __syncthreads();

    const int warp = tid >> 5, lane = tid & 31;
    float* pw = ps + warp * 64;

    for (int rr = 0; rr < 16; rr++) {
        int row = (warp << 4) + rr;
        const float* xrow = xq + row * XQ_PITCH;
        const float* k0 = kvs + lane * XQ_PITCH;
        const float* k1 = kvs + (lane + 32) * XQ_PITCH;
        float s0 = 0.0f, s1 = 0.0f;
#pragma unroll 8
        for (int d4 = 0; d4 < 32; d4++) {
            float4 xv = *(const float4*)&xrow[d4 << 2];
            float4 av = *(const float4*)&k0[d4 << 2];
            float4 bv = *(const float4*)&k1[d4 << 2];
            s0 += xv.x * av.x + xv.y * av.y + xv.z * av.z + xv.w * av.w;
            s1 += xv.x * bv.x + xv.y * bv.y + xv.z * bv.z + xv.w * bv.w;
        }
        // softmax over 64 values (2 per lane)
        float m = fmaxf(s0, s1);
#pragma unroll
        for (int off = 16; off > 0; off >>= 1)
            m = fmaxf(m, __shfl_xor_sync(0xffffffffu, m, off));
        float e0 = __expf(s0 - m), e1 = __expf(s1 - m);
        float sum = e0 + e1;
#pragma unroll
        for (int off = 16; off > 0; off >>= 1)
            sum += __shfl_xor_sync(0xffffffffu, sum, off);
        float inv = 1.0f / sum;
        __syncwarp();
        pw[lane] = e0 * inv;
        pw[lane + 32] = e1 * inv;
        __syncwarp();

        // out[d] = sum_r p[r] * kv[r][d]; each lane owns d = lane*4..lane*4+3
        float4 o = make_float4(0.f, 0.f, 0.f, 0.f);
#pragma unroll 16
        for (int r = 0; r < 64; r++) {
            float p = pw[r];
            float4 kvv = *(const float4*)&kvs[r * XQ_PITCH + (lane << 2)];
            o.x = fmaf(p, kvv.x, o.x);
            o.y = fmaf(p, kvv.y, o.y);
            o.z = fmaf(p, kvv.z, o.z);
            o.w = fmaf(p, kvv.w, o.w);
        }
        *(float4*)(C + (size_t)(rowBase + row) * HIDDEN + colBase + (lane << 2)) = o;
    }
}

// ---------------------------------------------------------------------------
// Host launcher
// ---------------------------------------------------------------------------
extern "C" void kernel_launch(void* const* d_in, const int* in_sizes, int n_in,
                              void* d_out, int out_size)
{
    const float* query = (const float*)d_in[0];
    const float* kvlat = (const float*)d_in[1];
    const float* wq    = (const float*)d_in[2];
    const float* wo    = (const float*)d_in[3];
    const float* w1    = (const float*)d_in[4];
    const float* b1    = (const float*)d_in[5];
    const float* w2    = (const float*)d_in[6];
    const float* b2    = (const float*)d_in[7];
    float* y = (float*)d_out;

    float *bufA = nullptr, *bufB = nullptr;
    cudaGetSymbolAddress((void**)&bufA, g_bufA);
    cudaGetSymbolAddress((void**)&bufB, g_bufB);

    const size_t fused_smem = FUSED_SMEM_FLOATS * sizeof(float);
    cudaFuncSetAttribute(fused_qk_attn_kernel,
                         cudaFuncAttributeMaxDynamicSharedMemorySize,
                         (int)fused_smem);

    const int grid = (SEQ / 128) * (HIDDEN / 128);  // 4096 blocks
    dim3 blk(256);

    // K1: bufA = attention(query @ wq)
    fused_qk_attn_kernel<<<grid, blk, fused_smem>>>(query, wq, kvlat, bufA);
    // K2: bufB = bufA @ wo                      ("out", kept fp32 for residual)
    gemm_kernel<false, false, false><<<grid, blk>>>(bufA, wo, nullptr, nullptr,
                                                    bufB, SEQ, HIDDEN, HIDDEN);
    // K3: bufA = gelu(bufB @ w1 + b1)
    gemm_kernel<true, true, false><<<grid, blk>>>(bufB, w1, b1, nullptr,
                                                  bufA, SEQ, HIDDEN, HIDDEN);
    // K4: y = bufA @ w2 + b2 + bufB
    gemm_kernel<true, false, true><<<grid, blk>>>(bufA, w2, b2, bufB,
                                                  y, SEQ, HIDDEN, HIDDEN);
}

// round 4
// speedup vs baseline: 6.0698x; 6.0698x over previous
#include <cuda_runtime.h>
#include <cuda_fp16.h>
#include <math.h>
#include <stdint.h>

#define SEQ    16384
#define HIDDEN 4096
#define NHEADS 32
#define RLAT   64

#define BM 128
#define BN 128
#define BK 32
#define APITCH 40     // fp16 elems per A smem row (80B: conflict-free ldmatrix)
#define BPITCH 136    // fp16 elems per B smem row
#define KTILES (HIDDEN / BK)   // 128

// ---------------- scratch (static device globals; no allocation) -----------
__device__ __half g_qh[(size_t)SEQ * HIDDEN];   // query fp16
__device__ __half g_ah[(size_t)SEQ * HIDDEN];   // attention out fp16
__device__ __half g_oh[(size_t)SEQ * HIDDEN];   // 'out' fp16
__device__ __half g_hh[(size_t)SEQ * HIDDEN];   // gelu hidden fp16
__device__ float  g_of[(size_t)SEQ * HIDDEN];   // 'out' fp32 (residual)
__device__ __half g_wqh[(size_t)HIDDEN * HIDDEN];
__device__ __half g_woh[(size_t)HIDDEN * HIDDEN];
__device__ __half g_w1h[(size_t)HIDDEN * HIDDEN];
__device__ __half g_w2h[(size_t)HIDDEN * HIDDEN];

// ---------------- small helpers -------------------------------------------
__device__ __forceinline__ uint32_t smem_u32(const void* p) {
    return (uint32_t)__cvta_generic_to_shared(p);
}
__device__ __forceinline__ void cp16(uint32_t s, const void* g) {
    asm volatile("cp.async.cg.shared.global [%0], [%1], 16;\n" :: "r"(s), "l"(g));
}
#define CP_COMMIT() asm volatile("cp.async.commit_group;\n")
#define CP_WAIT0()  asm volatile("cp.async.wait_group 0;\n")

__device__ __forceinline__ void ldsm4(uint32_t& r0, uint32_t& r1, uint32_t& r2,
                                      uint32_t& r3, uint32_t a) {
    asm volatile("ldmatrix.sync.aligned.m8n8.x4.shared.b16 {%0,%1,%2,%3}, [%4];\n"
                 : "=r"(r0), "=r"(r1), "=r"(r2), "=r"(r3) : "r"(a));
}
__device__ __forceinline__ void ldsm4t(uint32_t& r0, uint32_t& r1, uint32_t& r2,
                                       uint32_t& r3, uint32_t a) {
    asm volatile("ldmatrix.sync.aligned.m8n8.x4.trans.shared.b16 {%0,%1,%2,%3}, [%4];\n"
                 : "=r"(r0), "=r"(r1), "=r"(r2), "=r"(r3) : "r"(a));
}
__device__ __forceinline__ void mma16816(float* d, const uint32_t* a, const uint32_t* b) {
    asm volatile(
        "mma.sync.aligned.m16n8k16.row.col.f32.f16.f16.f32 "
        "{%0,%1,%2,%3}, {%4,%5,%6,%7}, {%8,%9}, {%0,%1,%2,%3};\n"
        : "+f"(d[0]), "+f"(d[1]), "+f"(d[2]), "+f"(d[3])
        : "r"(a[0]), "r"(a[1]), "r"(a[2]), "r"(a[3]), "r"(b[0]), "r"(b[1]));
}
__device__ __forceinline__ float gelu_exact(float x) {
    return 0.5f * x * (1.0f + erff(x * 0.70710678118654752f));
}

// ---------------- fp32 -> fp16 conversion ----------------------------------
__global__ __launch_bounds__(256)
void cvt_kernel(const float* __restrict__ in, __half* __restrict__ out, int n4) {
    int i = blockIdx.x * blockDim.x + threadIdx.x;
    int stride = gridDim.x * blockDim.x;
    for (; i < n4; i += stride) {
        float4 v = ((const float4*)in)[i];
        ((__half2*)out)[2 * i + 0] = __floats2half2_rn(v.x, v.y);
        ((__half2*)out)[2 * i + 1] = __floats2half2_rn(v.z, v.w);
    }
}

// ---------------- shared mainloop -----------------------------------------
// Computes acc[2][8][4] for this thread's fragments of the 128x128 tile.
// As/Bs are double-buffered fp16 smem tiles.
struct GemmCore {
    template <typename LdA, typename LdB>
    __device__ __forceinline__ static void run(
        float acc[2][8][4], __half* As, __half* Bs,
        const __half* Ap, const __half* Bp,
        int tid, int lane, int wm, int wn)
    {
        const int arow = tid >> 2, achk = tid & 3;    // A: 128 rows x 4 chunks
        const int brow = tid >> 4, bchk = tid & 15;   // B: 32 rows x 16 chunks

        // prefetch tile 0
        {
            __half* A0 = As; __half* B0 = Bs;
#pragma unroll
            for (int p = 0; p < 2; p++) {
                int r = arow + (p << 6);
                cp16(smem_u32(&A0[r * APITCH + achk * 8]),
                     Ap + (size_t)r * HIDDEN + achk * 8);
            }
#pragma unroll
            for (int p = 0; p < 2; p++) {
                int r = brow + (p << 4);
                cp16(smem_u32(&B0[r * BPITCH + bchk * 8]),
                     Bp + (size_t)r * HIDDEN + bchk * 8);
            }
            CP_COMMIT();
        }

        for (int t = 0; t < KTILES; t++) {
            CP_WAIT0();
            __syncthreads();
            if (t + 1 < KTILES) {
                int kt = (t + 1) * BK;
                __half* An = As + ((t + 1) & 1) * (BM * APITCH);
                __half* Bn = Bs + ((t + 1) & 1) * (BK * BPITCH);
#pragma unroll
                for (int p = 0; p < 2; p++) {
                    int r = arow + (p << 6);
                    cp16(smem_u32(&An[r * APITCH + achk * 8]),
                         Ap + (size_t)r * HIDDEN + kt + achk * 8);
                }
#pragma unroll
                for (int p = 0; p < 2; p++) {
                    int r = brow + (p << 4);
                    cp16(smem_u32(&Bn[r * BPITCH + bchk * 8]),
                         Bp + (size_t)(kt + r) * HIDDEN + bchk * 8);
                }
                CP_COMMIT();
            }
            __half* Ac = As + (t & 1) * (BM * APITCH);
            __half* Bc = Bs + (t & 1) * (BK * BPITCH);
#pragma unroll
            for (int ks = 0; ks < 2; ks++) {
                const int k0 = ks * 16;
                uint32_t a[2][4];
#pragma unroll
                for (int mi = 0; mi < 2; mi++) {
                    int m = wm * 32 + mi * 16 + (lane & 15);
                    ldsm4(a[mi][0], a[mi][1], a[mi][2], a[mi][3],
                          smem_u32(&Ac[m * APITCH + k0 + (lane >> 4) * 8]));
                }
                uint32_t b[4][4];
#pragma unroll
                for (int nj = 0; nj < 4; nj++) {
                    int kk = k0 + (lane & 15);
                    int n = wn * 64 + nj * 16 + (lane >> 4) * 8;
                    ldsm4t(b[nj][0], b[nj][1], b[nj][2], b[nj][3],
                           smem_u32(&Bc[kk * BPITCH + n]));
                }
#pragma unroll
                for (int mi = 0; mi < 2; mi++)
#pragma unroll
                    for (int nj = 0; nj < 4; nj++) {
                        mma16816(acc[mi][2 * nj + 0], a[mi], &b[nj][0]);
                        mma16816(acc[mi][2 * nj + 1], a[mi], &b[nj][2]);
                    }
            }
        }
    }
};

// ---------------- generic GEMM: C = epi(A @ B) -----------------------------
// OUTMODE: 0 = fp16 only, 1 = fp32 only, 2 = both
template <int OUTMODE, bool HASBIAS, bool GELU, bool RESID>
__global__ __launch_bounds__(256)
void hgemm_kernel(const __half* __restrict__ A, const __half* __restrict__ B,
                  const float* __restrict__ bias, const float* __restrict__ resid,
                  float* __restrict__ Cf, __half* __restrict__ Ch)
{
    __shared__ __align__(16) __half As[2 * BM * APITCH];
    __shared__ __align__(16) __half Bs[2 * BK * BPITCH];

    const int nyb = HIDDEN / BN;  // 32
    const int xb = blockIdx.x / nyb;
    const int yb = blockIdx.x % nyb;
    const int rowBase = xb * BM;
    const int colBase = yb * BN;

    const int tid = threadIdx.x;
    const int lane = tid & 31;
    const int warp = tid >> 5;
    const int wm = warp >> 1, wn = warp & 1;

    float acc[2][8][4];
#pragma unroll
    for (int i = 0; i < 2; i++)
#pragma unroll
        for (int j = 0; j < 8; j++)
#pragma unroll
            for (int k = 0; k < 4; k++) acc[i][j][k] = 0.0f;

    GemmCore::run<int, int>(acc, As, Bs,
                            A + (size_t)rowBase * HIDDEN, B + colBase,
                            tid, lane, wm, wn);

    // epilogue
#pragma unroll
    for (int mi = 0; mi < 2; mi++) {
        int r0 = rowBase + wm * 32 + mi * 16 + (lane >> 2);
#pragma unroll
        for (int nj = 0; nj < 8; nj++) {
            int col = colBase + wn * 64 + nj * 8 + (lane & 3) * 2;
            float v0 = acc[mi][nj][0], v1 = acc[mi][nj][1];
            float v2 = acc[mi][nj][2], v3 = acc[mi][nj][3];
            if (HASBIAS) {
                float2 bb = *(const float2*)&bias[col];
                v0 += bb.x; v1 += bb.y; v2 += bb.x; v3 += bb.y;
            }
            if (GELU) {
                v0 = gelu_exact(v0); v1 = gelu_exact(v1);
                v2 = gelu_exact(v2); v3 = gelu_exact(v3);
            }
            if (RESID) {
                float2 ra = *(const float2*)&resid[(size_t)r0 * HIDDEN + col];
                float2 rb = *(const float2*)&resid[(size_t)(r0 + 8) * HIDDEN + col];
                v0 += ra.x; v1 += ra.y; v2 += rb.x; v3 += rb.y;
            }
            if (OUTMODE >= 1) {
                *(float2*)&Cf[(size_t)r0 * HIDDEN + col] = make_float2(v0, v1);
                *(float2*)&Cf[(size_t)(r0 + 8) * HIDDEN + col] = make_float2(v2, v3);
            }
            if (OUTMODE == 0 || OUTMODE == 2) {
                *(__half2*)&Ch[(size_t)r0 * HIDDEN + col] = __floats2half2_rn(v0, v1);
                *(__half2*)&Ch[(size_t)(r0 + 8) * HIDDEN + col] = __floats2half2_rn(v2, v3);
            }
        }
    }
}

// ---------------- fused: xq = (q @ wq)*scale -> latent attention -----------
#define XQ_PITCH 132
#define FUSED_SMEM_BYTES ((128 * XQ_PITCH + 64 * XQ_PITCH + 8 * 64) * 4)

__global__ __launch_bounds__(256)
void fused_attn_kernel(const __half* __restrict__ A,   // query fp16 [SEQ,HIDDEN]
                       const __half* __restrict__ B,   // wq fp16 [HIDDEN,HIDDEN]
                       const float* __restrict__ kv,   // kv_latent fp32 [RLAT,HIDDEN]
                       __half* __restrict__ C)         // attn out fp16
{
    extern __shared__ __align__(16) char smem_raw[];
    __half* As = (__half*)smem_raw;
    __half* Bs = As + 2 * BM * APITCH;

    const int xb = blockIdx.x / NHEADS;
    const int h  = blockIdx.x % NHEADS;
    const int rowBase = xb * BM;
    const int colBase = h * 128;   // DH = 128 = BN

    const int tid = threadIdx.x;
    const int lane = tid & 31;
    const int warp = tid >> 5;
    const int wm = warp >> 1, wn = warp & 1;

    float acc[2][8][4];
#pragma unroll
    for (int i = 0; i < 2; i++)
#pragma unroll
        for (int j = 0; j < 8; j++)
#pragma unroll
            for (int k = 0; k < 4; k++) acc[i][j][k] = 0.0f;

    GemmCore::run<int, int>(acc, As, Bs,
                            A + (size_t)rowBase * HIDDEN, B + colBase,
                            tid, lane, wm, wn);

    __syncthreads();   // done with GEMM smem; repurpose for attention

    float* xq  = (float*)smem_raw;              // [128][XQ_PITCH]
    float* kvs = xq + 128 * XQ_PITCH;           // [64][XQ_PITCH]
    float* ps  = kvs + 64 * XQ_PITCH;           // [8][64]

    const float scale = 0.125f;  // R^-0.5
#pragma unroll
    for (int mi = 0; mi < 2; mi++) {
        int r0 = wm * 32 + mi * 16 + (lane >> 2);
#pragma unroll
        for (int nj = 0; nj < 8; nj++) {
            int c = wn * 64 + nj * 8 + (lane & 3) * 2;
            xq[r0 * XQ_PITCH + c]           = acc[mi][nj][0] * scale;
            xq[r0 * XQ_PITCH + c + 1]       = acc[mi][nj][1] * scale;
            xq[(r0 + 8) * XQ_PITCH + c]     = acc[mi][nj][2] * scale;
            xq[(r0 + 8) * XQ_PITCH + c + 1] = acc[mi][nj][3] * scale;
        }
    }
    for (int idx = tid; idx < RLAT * 32; idx += 256) {
        int r = idx >> 5, d4 = idx & 31;
        float4 v = *(const float4*)(kv + (size_t)r * HIDDEN + colBase + (d4 << 2));
        *(float4*)&kvs[r * XQ_PITCH + (d4 << 2)] = v;
    }
    __syncthreads();

    float* pw = ps + warp * 64;
    for (int rr = 0; rr < 16; rr++) {
        int row = (warp << 4) + rr;
        const float* xrow = xq + row * XQ_PITCH;
        const float* k0 = kvs + lane * XQ_PITCH;
        const float* k1 = kvs + (lane + 32) * XQ_PITCH;
        float s0 = 0.0f, s1 = 0.0f;
#pragma unroll 8
        for (int d4 = 0; d4 < 32; d4++) {
            float4 xv = *(const float4*)&xrow[d4 << 2];
            float4 av = *(const float4*)&k0[d4 << 2];
            float4 bv = *(const float4*)&k1[d4 << 2];
            s0 += xv.x * av.x + xv.y * av.y + xv.z * av.z + xv.w * av.w;
            s1 += xv.x * bv.x + xv.y * bv.y + xv.z * bv.z + xv.w * bv.w;
        }
        float m = fmaxf(s0, s1);
#pragma unroll
        for (int off = 16; off > 0; off >>= 1)
            m = fmaxf(m, __shfl_xor_sync(0xffffffffu, m, off));
        float e0 = __expf(s0 - m), e1 = __expf(s1 - m);
        float sum = e0 + e1;
#pragma unroll
        for (int off = 16; off > 0; off >>= 1)
            sum += __shfl_xor_sync(0xffffffffu, sum, off);
        float inv = 1.0f / sum;
        __syncwarp();
        pw[lane] = e0 * inv;
        pw[lane + 32] = e1 * inv;
        __syncwarp();

        float4 o = make_float4(0.f, 0.f, 0.f, 0.f);
#pragma unroll 16
        for (int r = 0; r < 64; r++) {
            float p = pw[r];
            float4 kvv = *(const float4*)&kvs[r * XQ_PITCH + (lane << 2)];
            o.x = fmaf(p, kvv.x, o.x);
            o.y = fmaf(p, kvv.y, o.y);
            o.z = fmaf(p, kvv.z, o.z);
            o.w = fmaf(p, kvv.w, o.w);
        }
        __half* cp = C + (size_t)(rowBase + row) * HIDDEN + colBase + (lane << 2);
        ((__half2*)cp)[0] = __floats2half2_rn(o.x, o.y);
        ((__half2*)cp)[1] = __floats2half2_rn(o.z, o.w);
    }
}

// ---------------- host launcher --------------------------------------------
extern "C" void kernel_launch(void* const* d_in, const int* in_sizes, int n_in,
                              void* d_out, int out_size)
{
    const float* query = (const float*)d_in[0];
    const float* kvlat = (const float*)d_in[1];
    const float* wq    = (const float*)d_in[2];
    const float* wo    = (const float*)d_in[3];
    const float* w1    = (const float*)d_in[4];
    const float* b1    = (const float*)d_in[5];
    const float* w2    = (const float*)d_in[6];
    const float* b2    = (const float*)d_in[7];
    float* y = (float*)d_out;

    __half *qh, *ah, *oh, *hh, *wqh, *woh, *w1h, *w2h;
    float* of;
    cudaGetSymbolAddress((void**)&qh, g_qh);
    cudaGetSymbolAddress((void**)&ah, g_ah);
    cudaGetSymbolAddress((void**)&oh, g_oh);
    cudaGetSymbolAddress((void**)&hh, g_hh);
    cudaGetSymbolAddress((void**)&of, g_of);
    cudaGetSymbolAddress((void**)&wqh, g_wqh);
    cudaGetSymbolAddress((void**)&woh, g_woh);
    cudaGetSymbolAddress((void**)&w1h, g_w1h);
    cudaGetSymbolAddress((void**)&w2h, g_w2h);

    cudaFuncSetAttribute(fused_attn_kernel,
                         cudaFuncAttributeMaxDynamicSharedMemorySize,
                         FUSED_SMEM_BYTES);

    const int wn4 = (HIDDEN * HIDDEN) / 4;
    const int qn4 = (SEQ * HIDDEN) / 4;
    cvt_kernel<<<4096, 256>>>(query, qh, qn4);
    cvt_kernel<<<4096, 256>>>(wq, wqh, wn4);
    cvt_kernel<<<4096, 256>>>(wo, woh, wn4);
    cvt_kernel<<<4096, 256>>>(w1, w1h, wn4);
    cvt_kernel<<<4096, 256>>>(w2, w2h, wn4);

    const int grid = (SEQ / BM) * (HIDDEN / BN);  // 4096
    dim3 blk(256);

    // K1: ah = attention(q @ wq)
    fused_attn_kernel<<<grid, blk, FUSED_SMEM_BYTES>>>(qh, wqh, kvlat, ah);
    // K2: out = ah @ wo  -> fp32 (residual) + fp16 (next GEMM input)
    hgemm_kernel<2, false, false, false><<<grid, blk>>>(ah, woh, nullptr, nullptr,
                                                        of, oh);
    // K3: hh = gelu(out @ w1 + b1) -> fp16
    hgemm_kernel<0, true, true, false><<<grid, blk>>>(oh, w1h, b1, nullptr,
                                                      nullptr, hh);
    // K4: y = hh @ w2 + b2 + out  -> fp32
    hgemm_kernel<1, true, false, true><<<grid, blk>>>(hh, w2h, b2, of,
                                                      y, nullptr);
}

// round 8
// speedup vs baseline: 6.5452x; 1.0783x over previous
#include <cuda_runtime.h>
#include <cuda_fp16.h>
#include <math.h>
#include <stdint.h>

#define SEQ    16384
#define HIDDEN 4096
#define NHEADS 32
#define RLAT   64

#define BM 128
#define BN 128
#define BK 32
#define NSTAGE 4
#define APITCH 40     // fp16 elems per A smem row (80B: conflict-free ldmatrix)
#define BPITCH 136    // fp16 elems per B smem row
#define KTILES (HIDDEN / BK)   // 128

#define A_ST (BM * APITCH)     // halves per A stage
#define B_ST (BK * BPITCH)     // halves per B stage
#define GEMM_SMEM_BYTES ((NSTAGE * (A_ST + B_ST)) * 2)   // 75,776 B

// ---------------- scratch (static device globals; no allocation) -----------
__device__ __half g_qh[(size_t)SEQ * HIDDEN];   // query fp16
__device__ __half g_ah[(size_t)SEQ * HIDDEN];   // attention out fp16
__device__ __half g_oh[(size_t)SEQ * HIDDEN];   // 'out' fp16
__device__ __half g_hh[(size_t)SEQ * HIDDEN];   // gelu hidden fp16
__device__ float  g_of[(size_t)SEQ * HIDDEN];   // 'out' fp32 (residual)
__device__ __half g_wqh[(size_t)HIDDEN * HIDDEN];
__device__ __half g_woh[(size_t)HIDDEN * HIDDEN];
__device__ __half g_w1h[(size_t)HIDDEN * HIDDEN];
__device__ __half g_w2h[(size_t)HIDDEN * HIDDEN];

// ---------------- small helpers -------------------------------------------
__device__ __forceinline__ uint32_t smem_u32(const void* p) {
    return (uint32_t)__cvta_generic_to_shared(p);
}
__device__ __forceinline__ void cp16(uint32_t s, const void* g) {
    asm volatile("cp.async.cg.shared.global [%0], [%1], 16;\n" :: "r"(s), "l"(g));
}
#define CP_COMMIT() asm volatile("cp.async.commit_group;\n")
#define CP_WAIT2()  asm volatile("cp.async.wait_group 2;\n")

__device__ __forceinline__ void ldsm4(uint32_t& r0, uint32_t& r1, uint32_t& r2,
                                      uint32_t& r3, uint32_t a) {
    asm volatile("ldmatrix.sync.aligned.m8n8.x4.shared.b16 {%0,%1,%2,%3}, [%4];\n"
                 : "=r"(r0), "=r"(r1), "=r"(r2), "=r"(r3) : "r"(a));
}
__device__ __forceinline__ void ldsm4t(uint32_t& r0, uint32_t& r1, uint32_t& r2,
                                       uint32_t& r3, uint32_t a) {
    asm volatile("ldmatrix.sync.aligned.m8n8.x4.trans.shared.b16 {%0,%1,%2,%3}, [%4];\n"
                 : "=r"(r0), "=r"(r1), "=r"(r2), "=r"(r3) : "r"(a));
}
__device__ __forceinline__ void mma16816(float* d, const uint32_t* a, const uint32_t* b) {
    asm volatile(
        "mma.sync.aligned.m16n8k16.row.col.f32.f16.f16.f32 "
        "{%0,%1,%2,%3}, {%4,%5,%6,%7}, {%8,%9}, {%0,%1,%2,%3};\n"
        : "+f"(d[0]), "+f"(d[1]), "+f"(d[2]), "+f"(d[3])
        : "r"(a[0]), "r"(a[1]), "r"(a[2]), "r"(a[3]), "r"(b[0]), "r"(b[1]));
}
__device__ __forceinline__ float gelu_exact(float x) {
    return 0.5f * x * (1.0f + erff(x * 0.70710678118654752f));
}

// ---------------- fp32 -> fp16 conversion ----------------------------------
__global__ __launch_bounds__(256)
void cvt_kernel(const float* __restrict__ in, __half* __restrict__ out, int n4) {
    int i = blockIdx.x * blockDim.x + threadIdx.x;
    int stride = gridDim.x * blockDim.x;
    for (; i < n4; i += stride) {
        float4 v = ((const float4*)in)[i];
        ((__half2*)out)[2 * i + 0] = __floats2half2_rn(v.x, v.y);
        ((__half2*)out)[2 * i + 1] = __floats2half2_rn(v.z, v.w);
    }
}

// ---------------- shared mainloop: 4-stage cp.async pipeline ----------------
// Computes acc[2][8][4] for this thread's fragments of the 128x128 tile.
// Asm/Bsm point to NSTAGE-deep stage arrays in dynamic smem.
struct GemmCore {
    __device__ __forceinline__ static void load_tile(
        __half* Asm, __half* Bsm, int u,
        const __half* Ap, const __half* Bp, int arow, int achk, int brow, int bchk)
    {
        __half* A0 = Asm + (u & (NSTAGE - 1)) * A_ST;
        __half* B0 = Bsm + (u & (NSTAGE - 1)) * B_ST;
        const int kt = u * BK;
#pragma unroll
        for (int p = 0; p < 2; p++) {
            int r = arow + (p << 6);
            cp16(smem_u32(&A0[r * APITCH + achk * 8]),
                 Ap + (size_t)r * HIDDEN + kt + achk * 8);
        }
#pragma unroll
        for (int p = 0; p < 2; p++) {
            int kk = brow + (p << 4);
            cp16(smem_u32(&B0[kk * BPITCH + bchk * 8]),
                 Bp + (size_t)(kt + kk) * HIDDEN + bchk * 8);
        }
    }

    __device__ __forceinline__ static void run(
        float acc[2][8][4], __half* Asm, __half* Bsm,
        const __half* Ap, const __half* Bp,
        int tid, int lane, int wm, int wn)
    {
        const int arow = tid >> 2, achk = tid & 3;    // A: 128 rows x 4 chunks
        const int brow = tid >> 4, bchk = tid & 15;   // B: 32 rows x 16 chunks

        // prologue: tiles 0..NSTAGE-2 (one commit group each)
#pragma unroll
        for (int u = 0; u < NSTAGE - 1; u++) {
            load_tile(Asm, Bsm, u, Ap, Bp, arow, achk, brow, bchk);
            CP_COMMIT();
        }

        for (int t = 0; t < KTILES; t++) {
            // group for tile t has exactly (NSTAGE-2)=2 groups after it
            CP_WAIT2();
            __syncthreads();

            // refill stage (t-1)&3 with tile t+3 (all warps done with t-1)
            int un = t + NSTAGE - 1;
            if (un < KTILES)
                load_tile(Asm, Bsm, un, Ap, Bp, arow, achk, brow, bchk);
            CP_COMMIT();   // empty group in tail keeps wait depth uniform

            __half* Ac = Asm + (t & (NSTAGE - 1)) * A_ST;
            __half* Bc = Bsm + (t & (NSTAGE - 1)) * B_ST;
#pragma unroll
            for (int ks = 0; ks < 2; ks++) {
                const int k0 = ks * 16;
                uint32_t a[2][4];
#pragma unroll
                for (int mi = 0; mi < 2; mi++) {
                    int m = wm * 32 + mi * 16 + (lane & 15);
                    ldsm4(a[mi][0], a[mi][1], a[mi][2], a[mi][3],
                          smem_u32(&Ac[m * APITCH + k0 + (lane >> 4) * 8]));
                }
                uint32_t b[4][4];
#pragma unroll
                for (int nj = 0; nj < 4; nj++) {
                    int kk = k0 + (lane & 15);
                    int n = wn * 64 + nj * 16 + (lane >> 4) * 8;
                    ldsm4t(b[nj][0], b[nj][1], b[nj][2], b[nj][3],
                           smem_u32(&Bc[kk * BPITCH + n]));
                }
#pragma unroll
                for (int mi = 0; mi < 2; mi++)
#pragma unroll
                    for (int nj = 0; nj < 4; nj++) {
                        mma16816(acc[mi][2 * nj + 0], a[mi], &b[nj][0]);
                        mma16816(acc[mi][2 * nj + 1], a[mi], &b[nj][2]);
                    }
            }
        }
    }
};

// ---------------- generic GEMM: C = epi(A @ B) -----------------------------
// OUTMODE: 0 = fp16 only, 1 = fp32 only, 2 = both
template <int OUTMODE, bool HASBIAS, bool GELU, bool RESID>
__global__ __launch_bounds__(256, 2)
void hgemm_kernel(const __half* __restrict__ A, const __half* __restrict__ B,
                  const float* __restrict__ bias, const float* __restrict__ resid,
                  float* __restrict__ Cf, __half* __restrict__ Ch)
{
    extern __shared__ __align__(16) char dsm[];
    __half* Asm = (__half*)dsm;
    __half* Bsm = Asm + NSTAGE * A_ST;

    const int nyb = HIDDEN / BN;  // 32
    const int xb = blockIdx.x / nyb;
    const int yb = blockIdx.x % nyb;
    const int rowBase = xb * BM;
    const int colBase = yb * BN;

    const int tid = threadIdx.x;
    const int lane = tid & 31;
    const int warp = tid >> 5;
    const int wm = warp >> 1, wn = warp & 1;

    float acc[2][8][4];
#pragma unroll
    for (int i = 0; i < 2; i++)
#pragma unroll
        for (int j = 0; j < 8; j++)
#pragma unroll
            for (int k = 0; k < 4; k++) acc[i][j][k] = 0.0f;

    GemmCore::run(acc, Asm, Bsm,
                  A + (size_t)rowBase * HIDDEN, B + colBase,
                  tid, lane, wm, wn);

    // epilogue
#pragma unroll
    for (int mi = 0; mi < 2; mi++) {
        int r0 = rowBase + wm * 32 + mi * 16 + (lane >> 2);
#pragma unroll
        for (int nj = 0; nj < 8; nj++) {
            int col = colBase + wn * 64 + nj * 8 + (lane & 3) * 2;
            float v0 = acc[mi][nj][0], v1 = acc[mi][nj][1];
            float v2 = acc[mi][nj][2], v3 = acc[mi][nj][3];
            if (HASBIAS) {
                float2 bb = *(const float2*)&bias[col];
                v0 += bb.x; v1 += bb.y; v2 += bb.x; v3 += bb.y;
            }
            if (GELU) {
                v0 = gelu_exact(v0); v1 = gelu_exact(v1);
                v2 = gelu_exact(v2); v3 = gelu_exact(v3);
            }
            if (RESID) {
                float2 ra = *(const float2*)&resid[(size_t)r0 * HIDDEN + col];
                float2 rb = *(const float2*)&resid[(size_t)(r0 + 8) * HIDDEN + col];
                v0 += ra.x; v1 += ra.y; v2 += rb.x; v3 += rb.y;
            }
            if (OUTMODE >= 1) {
                *(float2*)&Cf[(size_t)r0 * HIDDEN + col] = make_float2(v0, v1);
                *(float2*)&Cf[(size_t)(r0 + 8) * HIDDEN + col] = make_float2(v2, v3);
            }
            if (OUTMODE == 0 || OUTMODE == 2) {
                *(__half2*)&Ch[(size_t)r0 * HIDDEN + col] = __floats2half2_rn(v0, v1);
                *(__half2*)&Ch[(size_t)(r0 + 8) * HIDDEN + col] = __floats2half2_rn(v2, v3);
            }
        }
    }
}

// ---------------- fused: xq = (q @ wq)*scale -> latent attention -----------
#define XQ_PITCH 132
#define ATTN_BODY_BYTES ((128 * XQ_PITCH + 64 * XQ_PITCH + 8 * 64) * 4)
#define ATTN_SMEM_BYTES (ATTN_BODY_BYTES > GEMM_SMEM_BYTES ? ATTN_BODY_BYTES : GEMM_SMEM_BYTES)

__global__ __launch_bounds__(256, 2)
void fused_attn_kernel(const __half* __restrict__ A,   // query fp16 [SEQ,HIDDEN]
                       const __half* __restrict__ B,   // wq fp16 [HIDDEN,HIDDEN]
                       const float* __restrict__ kv,   // kv_latent fp32 [RLAT,HIDDEN]
                       __half* __restrict__ C)         // attn out fp16
{
    extern __shared__ __align__(16) char smem_raw[];
    __half* Asm = (__half*)smem_raw;
    __half* Bsm = Asm + NSTAGE * A_ST;

    const int xb = blockIdx.x / NHEADS;
    const int h  = blockIdx.x % NHEADS;
    const int rowBase = xb * BM;
    const int colBase = h * 128;   // DH = 128 = BN

    const int tid = threadIdx.x;
    const int lane = tid & 31;
    const int warp = tid >> 5;
    const int wm = warp >> 1, wn = warp & 1;

    float acc[2][8][4];
#pragma unroll
    for (int i = 0; i < 2; i++)
#pragma unroll
        for (int j = 0; j < 8; j++)
#pragma unroll
            for (int k = 0; k < 4; k++) acc[i][j][k] = 0.0f;

    GemmCore::run(acc, Asm, Bsm,
                  A + (size_t)rowBase * HIDDEN, B + colBase,
                  tid, lane, wm, wn);

    __syncthreads();   // done with GEMM smem; repurpose for attention

    float* xq  = (float*)smem_raw;              // [128][XQ_PITCH]
    float* kvs = xq + 128 * XQ_PITCH;           // [64][XQ_PITCH]
    float* ps  = kvs + 64 * XQ_PITCH;           // [8][64]

    const float scale = 0.125f;  // R^-0.5
#pragma unroll
    for (int mi = 0; mi < 2; mi++) {
        int r0 = wm * 32 + mi * 16 + (lane >> 2);
#pragma unroll
        for (int nj = 0; nj < 8; nj++) {
            int c = wn * 64 + nj * 8 + (lane & 3) * 2;
            xq[r0 * XQ_PITCH + c]           = acc[mi][nj][0] * scale;
            xq[r0 * XQ_PITCH + c + 1]       = acc[mi][nj][1] * scale;
            xq[(r0 + 8) * XQ_PITCH + c]     = acc[mi][nj][2] * scale;
            xq[(r0 + 8) * XQ_PITCH + c + 1] = acc[mi][nj][3] * scale;
        }
    }
    for (int idx = tid; idx < RLAT * 32; idx += 256) {
        int r = idx >> 5, d4 = idx & 31;
        float4 v = *(const float4*)(kv + (size_t)r * HIDDEN + colBase + (d4 << 2));
        *(float4*)&kvs[r * XQ_PITCH + (d4 << 2)] = v;
    }
    __syncthreads();

    float* pw = ps + warp * 64;
    for (int rr = 0; rr < 16; rr++) {
        int row = (warp << 4) + rr;
        const float* xrow = xq + row * XQ_PITCH;
        const float* k0 = kvs + lane * XQ_PITCH;
        const float* k1 = kvs + (lane + 32) * XQ_PITCH;
        float s0 = 0.0f, s1 = 0.0f;
#pragma unroll 8
        for (int d4 = 0; d4 < 32; d4++) {
            float4 xv = *(const float4*)&xrow[d4 << 2];
            float4 av = *(const float4*)&k0[d4 << 2];
            float4 bv = *(const float4*)&k1[d4 << 2];
            s0 += xv.x * av.x + xv.y * av.y + xv.z * av.z + xv.w * av.w;
            s1 += xv.x * bv.x + xv.y * bv.y + xv.z * bv.z + xv.w * bv.w;
        }
        float m = fmaxf(s0, s1);
#pragma unroll
        for (int off = 16; off > 0; off >>= 1)
            m = fmaxf(m, __shfl_xor_sync(0xffffffffu, m, off));
        float e0 = __expf(s0 - m), e1 = __expf(s1 - m);
        float sum = e0 + e1;
#pragma unroll
        for (int off = 16; off > 0; off >>= 1)
            sum += __shfl_xor_sync(0xffffffffu, sum, off);
        float inv = 1.0f / sum;
        __syncwarp();
        pw[lane] = e0 * inv;
        pw[lane + 32] = e1 * inv;
        __syncwarp();

        float4 o = make_float4(0.f, 0.f, 0.f, 0.f);
#pragma unroll 16
        for (int r = 0; r < 64; r++) {
            float p = pw[r];
            float4 kvv = *(const float4*)&kvs[r * XQ_PITCH + (lane << 2)];
            o.x = fmaf(p, kvv.x, o.x);
            o.y = fmaf(p, kvv.y, o.y);
            o.z = fmaf(p, kvv.z, o.z);
            o.w = fmaf(p, kvv.w, o.w);
        }
        __half* cp = C + (size_t)(rowBase + row) * HIDDEN + colBase + (lane << 2);
        ((__half2*)cp)[0] = __floats2half2_rn(o.x, o.y);
        ((__half2*)cp)[1] = __floats2half2_rn(o.z, o.w);
    }
}

// ---------------- host launcher --------------------------------------------
extern "C" void kernel_launch(void* const* d_in, const int* in_sizes, int n_in,
                              void* d_out, int out_size)
{
    const float* query = (const float*)d_in[0];
    const float* kvlat = (const float*)d_in[1];
    const float* wq    = (const float*)d_in[2];
    const float* wo    = (const float*)d_in[3];
    const float* w1    = (const float*)d_in[4];
    const float* b1    = (const float*)d_in[5];
    const float* w2    = (const float*)d_in[6];
    const float* b2    = (const float*)d_in[7];
    float* y = (float*)d_out;

    __half *qh, *ah, *oh, *hh, *wqh, *woh, *w1h, *w2h;
    float* of;
    cudaGetSymbolAddress((void**)&qh, g_qh);
    cudaGetSymbolAddress((void**)&ah, g_ah);
    cudaGetSymbolAddress((void**)&oh, g_oh);
    cudaGetSymbolAddress((void**)&hh, g_hh);
    cudaGetSymbolAddress((void**)&of, g_of);
    cudaGetSymbolAddress((void**)&wqh, g_wqh);
    cudaGetSymbolAddress((void**)&woh, g_woh);
    cudaGetSymbolAddress((void**)&w1h, g_w1h);
    cudaGetSymbolAddress((void**)&w2h, g_w2h);

    cudaFuncSetAttribute(fused_attn_kernel,
                         cudaFuncAttributeMaxDynamicSharedMemorySize,
                         ATTN_SMEM_BYTES);
    cudaFuncSetAttribute(hgemm_kernel<2, false, false, false>,
                         cudaFuncAttributeMaxDynamicSharedMemorySize,
                         GEMM_SMEM_BYTES);
    cudaFuncSetAttribute(hgemm_kernel<0, true, true, false>,
                         cudaFuncAttributeMaxDynamicSharedMemorySize,
                         GEMM_SMEM_BYTES);
    cudaFuncSetAttribute(hgemm_kernel<1, true, false, true>,
                         cudaFuncAttributeMaxDynamicSharedMemorySize,
                         GEMM_SMEM_BYTES);

    const int wn4 = (HIDDEN * HIDDEN) / 4;
    const int qn4 = (SEQ * HIDDEN) / 4;
    cvt_kernel<<<4096, 256>>>(query, qh, qn4);
    cvt_kernel<<<4096, 256>>>(wq, wqh, wn4);
    cvt_kernel<<<4096, 256>>>(wo, woh, wn4);
    cvt_kernel<<<4096, 256>>>(w1, w1h, wn4);
    cvt_kernel<<<4096, 256>>>(w2, w2h, wn4);

    const int grid = (SEQ / BM) * (HIDDEN / BN);  // 4096
    dim3 blk(256);

    // K1: ah = attention(q @ wq)
    fused_attn_kernel<<<grid, blk, ATTN_SMEM_BYTES>>>(qh, wqh, kvlat, ah);
    // K2: out = ah @ wo  -> fp32 (residual) + fp16 (next GEMM input)
    hgemm_kernel<2, false, false, false><<<grid, blk, GEMM_SMEM_BYTES>>>(
        ah, woh, nullptr, nullptr, of, oh);
    // K3: hh = gelu(out @ w1 + b1) -> fp16
    hgemm_kernel<0, true, true, false><<<grid, blk, GEMM_SMEM_BYTES>>>(
        oh, w1h, b1, nullptr, nullptr, hh);
    // K4: y = hh @ w2 + b2 + out  -> fp32
    hgemm_kernel<1, true, false, true><<<grid, blk, GEMM_SMEM_BYTES>>>(
        hh, w2h, b2, of, y, nullptr);
}